// round 1
// baseline (speedup 1.0000x reference)
#include <cuda_runtime.h>
#include <cuda_bf16.h>
#include <math.h>

#define N_NODES 10000
#define N_EDGES 160000
#define N_FEAT  512
#define HEADS   8
#define HID     128
#define NH      (HEADS * HID)   // 1024

// ---------------- scratch (device globals; no allocations allowed) ----------
__device__ float g_h[(size_t)N_NODES * NH];        // projected features [N,H,D]
__device__ float g_emb1[(size_t)N_NODES * HID];
__device__ float g_emb2[(size_t)N_NODES * HID];
__device__ float g_si[N_NODES * HEADS];
__device__ float g_sj[N_NODES * HEADS];
__device__ int   g_deg[N_NODES];
__device__ int   g_off[N_NODES + 1];
__device__ int   g_cur[N_NODES];
__device__ int   g_csr[N_EDGES];
__device__ float g_part[128 * HID];
__device__ float g_gvec[HID];

// ---------------- CSR construction ----------------
__global__ void init_deg_kernel() {
    int i = blockIdx.x * blockDim.x + threadIdx.x;
    if (i < N_NODES) g_deg[i] = 0;
}

__global__ void hist_kernel(const int* __restrict__ dst) {
    int e = blockIdx.x * blockDim.x + threadIdx.x;
    if (e < N_EDGES) atomicAdd(&g_deg[dst[e]], 1);
}

__global__ void scan_kernel() {
    __shared__ int sums[1024];
    int t = threadIdx.x;
    const int CH = (N_NODES + 1023) / 1024;   // 10
    int start = t * CH;
    int s = 0;
    for (int i = 0; i < CH; i++) {
        int idx = start + i;
        if (idx < N_NODES) s += g_deg[idx];
    }
    sums[t] = s;
    __syncthreads();
    for (int st = 1; st < 1024; st <<= 1) {
        int v = (t >= st) ? sums[t - st] : 0;
        __syncthreads();
        sums[t] += v;
        __syncthreads();
    }
    int base = (t == 0) ? 0 : sums[t - 1];
    for (int i = 0; i < CH; i++) {
        int idx = start + i;
        if (idx < N_NODES) {
            g_off[idx] = base;
            g_cur[idx] = base;
            base += g_deg[idx];
        }
    }
    if (t == 1023) g_off[N_NODES] = sums[1023];
}

__global__ void fill_kernel(const int* __restrict__ src, const int* __restrict__ dst) {
    int e = blockIdx.x * blockDim.x + threadIdx.x;
    if (e < N_EDGES) {
        int pos = atomicAdd(&g_cur[dst[e]], 1);
        g_csr[pos] = src[e];
    }
}

// ---------------- SGEMM: C[m,n] = sum_k A[m,k] * B[n,k]  (NT, fp32) --------
// C is always g_h. A is either the kernel arg (layer 1) or g_emb1 (layer 2).
#define BM 128
#define BN 128
#define BK 16
#define TM 8
#define TN 8

template<bool A_FROM_ARG>
__global__ __launch_bounds__(256)
void sgemm_nt(const float* __restrict__ Aarg, const float* __restrict__ B,
              int M, int N, int K) {
    const float* A = A_FROM_ARG ? Aarg : g_emb1;
    float* C = g_h;

    __shared__ float As[BK][BM];
    __shared__ float Bs[BK][BN];

    int tid = threadIdx.x;
    int bm = blockIdx.y * BM;
    int bn = blockIdx.x * BN;
    int tx = tid % 16, ty = tid / 16;

    float acc[TM][TN];
    #pragma unroll
    for (int i = 0; i < TM; i++)
        #pragma unroll
        for (int j = 0; j < TN; j++) acc[i][j] = 0.f;

    int lr = tid / 4;            // 0..63
    int lc = (tid % 4) * 4;      // 0,4,8,12

    for (int k0 = 0; k0 < K; k0 += BK) {
        #pragma unroll
        for (int rep = 0; rep < 2; rep++) {
            int row = lr + rep * 64;
            int gm = bm + row;
            float4 v = make_float4(0.f, 0.f, 0.f, 0.f);
            if (gm < M)
                v = *reinterpret_cast<const float4*>(&A[(size_t)gm * K + k0 + lc]);
            As[lc + 0][row] = v.x; As[lc + 1][row] = v.y;
            As[lc + 2][row] = v.z; As[lc + 3][row] = v.w;
            int gn = bn + row;   // N is always multiple of 128 here
            float4 w = *reinterpret_cast<const float4*>(&B[(size_t)gn * K + k0 + lc]);
            Bs[lc + 0][row] = w.x; Bs[lc + 1][row] = w.y;
            Bs[lc + 2][row] = w.z; Bs[lc + 3][row] = w.w;
        }
        __syncthreads();
        #pragma unroll
        for (int kk = 0; kk < BK; kk++) {
            float af[TM], bf[TN];
            #pragma unroll
            for (int i = 0; i < TM; i++) af[i] = As[kk][ty * TM + i];
            #pragma unroll
            for (int j = 0; j < TN; j++) bf[j] = Bs[kk][tx * TN + j];
            #pragma unroll
            for (int i = 0; i < TM; i++)
                #pragma unroll
                for (int j = 0; j < TN; j++)
                    acc[i][j] += af[i] * bf[j];
        }
        __syncthreads();
    }

    #pragma unroll
    for (int i = 0; i < TM; i++) {
        int gm = bm + ty * TM + i;
        if (gm >= M) continue;
        #pragma unroll
        for (int j = 0; j < TN; j += 4) {
            float4 v = make_float4(acc[i][j], acc[i][j + 1], acc[i][j + 2], acc[i][j + 3]);
            *reinterpret_cast<float4*>(&C[(size_t)gm * N + bn + tx * TN + j]) = v;
        }
    }
}

// ---------------- attention scores: s_i / s_j per (node, head) -------------
__global__ void scores_kernel(const float* __restrict__ a) {
    int gw = (blockIdx.x * blockDim.x + threadIdx.x) >> 5;
    int lane = threadIdx.x & 31;
    if (gw >= N_NODES * HEADS) return;
    int n = gw / HEADS, hd = gw % HEADS;
    const float* hp = g_h + ((size_t)n * HEADS + hd) * HID;
    const float* ap = a + hd * 2 * HID;
    float s1 = 0.f, s2 = 0.f;
    #pragma unroll
    for (int j = 0; j < HID / 32; j++) {
        int d = lane + 32 * j;
        float v = hp[d];
        s1 += v * ap[d];
        s2 += v * ap[HID + d];
    }
    #pragma unroll
    for (int o = 16; o; o >>= 1) {
        s1 += __shfl_down_sync(0xffffffffu, s1, o);
        s2 += __shfl_down_sync(0xffffffffu, s2, o);
    }
    if (lane == 0) { g_si[gw] = s1; g_sj[gw] = s2; }
}

// ---------------- aggregation: segment softmax + weighted gather -----------
// one block per dst node; warp w = head w; online softmax over edge chunks
template<int OUT>
__global__ __launch_bounds__(256)
void aggregate_kernel() {
    int n = blockIdx.x;
    int w = threadIdx.x >> 5;
    int lane = threadIdx.x & 31;
    __shared__ float part[HEADS][HID];

    int off = g_off[n], end = g_off[n + 1];
    float si_v = g_si[n * HEADS + w];
    float4 acc = make_float4(0.f, 0.f, 0.f, 0.f);
    float m_run = -INFINITY, d_run = 0.f;

    for (int base = off; base < end; base += 32) {
        int e = base + lane;
        int src = 0;
        float ev = -INFINITY;
        if (e < end) {
            src = g_csr[e];
            float x = si_v + g_sj[src * HEADS + w];
            ev = (x > 0.f) ? x : 0.01f * x;
        }
        float cm = ev;
        #pragma unroll
        for (int o = 16; o; o >>= 1) cm = fmaxf(cm, __shfl_xor_sync(0xffffffffu, cm, o));
        float new_m = fmaxf(m_run, cm);
        float p = (e < end) ? __expf(ev - new_m) : 0.f;
        float ps = p;
        #pragma unroll
        for (int o = 16; o; o >>= 1) ps += __shfl_xor_sync(0xffffffffu, ps, o);
        float scale = (m_run == -INFINITY) ? 0.f : __expf(m_run - new_m);
        d_run = d_run * scale + ps;
        acc.x *= scale; acc.y *= scale; acc.z *= scale; acc.w *= scale;
        m_run = new_m;

        int cnt = min(32, end - base);
        for (int j = 0; j < cnt; j++) {
            float pj = __shfl_sync(0xffffffffu, p, j);
            int sidx = __shfl_sync(0xffffffffu, src, j);
            const float4 v = *reinterpret_cast<const float4*>(
                &g_h[((size_t)sidx * HEADS + w) * HID + lane * 4]);
            acc.x += pj * v.x; acc.y += pj * v.y;
            acc.z += pj * v.z; acc.w += pj * v.w;
        }
    }
    if (d_run > 0.f) {
        float inv = 1.f / d_run;
        acc.x *= inv; acc.y *= inv; acc.z *= inv; acc.w *= inv;
    }
    part[w][lane * 4 + 0] = acc.x;
    part[w][lane * 4 + 1] = acc.y;
    part[w][lane * 4 + 2] = acc.z;
    part[w][lane * 4 + 3] = acc.w;
    __syncthreads();

    if (threadIdx.x < HID) {
        int d = threadIdx.x;
        float s = 0.f;
        #pragma unroll
        for (int hh = 0; hh < HEADS; hh++) s += part[hh][d];
        s *= (1.f / HEADS);
        float o = (s > 0.f) ? s : (__expf(s) - 1.f);   // ELU
        float* emb = (OUT == 1) ? g_emb1 : g_emb2;
        emb[(size_t)n * HID + d] = o;
    }
}

// ---------------- graph mean pooling ----------------
__global__ void pool_stage1() {
    const int RP = (N_NODES + 127) / 128;   // 79
    int b = blockIdx.x, d = threadIdx.x;
    int r0 = b * RP;
    int r1 = min(r0 + RP, N_NODES);
    float s = 0.f;
    for (int r = r0; r < r1; r++) s += g_emb2[(size_t)r * HID + d];
    g_part[b * HID + d] = s;
}

__global__ void pool_stage2() {
    int d = threadIdx.x;
    float s = 0.f;
    for (int b = 0; b < 128; b++) s += g_part[b * HID + d];
    g_gvec[d] = s * (1.f / N_NODES);
}

// ---------------- MLP head ----------------
__global__ void mlp_kernel(const float* __restrict__ ln_g, const float* __restrict__ ln_b,
                           const float* __restrict__ Wl1, const float* __restrict__ bl1,
                           const float* __restrict__ Wl2, const float* __restrict__ bl2,
                           const float* __restrict__ Wl3, const float* __restrict__ bl3,
                           float* __restrict__ out) {
    __shared__ float gn[HID];
    __shared__ float x1[64];
    __shared__ float x2[16];
    __shared__ float red[128];
    int t = threadIdx.x;  // 128 threads
    float gv = g_gvec[t];

    red[t] = gv;
    __syncthreads();
    for (int st = 64; st; st >>= 1) {
        if (t < st) red[t] += red[t + st];
        __syncthreads();
    }
    float mu = red[0] * (1.f / HID);
    __syncthreads();

    float dv = gv - mu;
    red[t] = dv * dv;
    __syncthreads();
    for (int st = 64; st; st >>= 1) {
        if (t < st) red[t] += red[t + st];
        __syncthreads();
    }
    float var = red[0] * (1.f / HID);
    gn[t] = dv * rsqrtf(var + 1e-5f) * ln_g[t] + ln_b[t];
    __syncthreads();

    if (t < 64) {
        float s = bl1[t];
        for (int k = 0; k < HID; k++) s += Wl1[t * HID + k] * gn[k];
        x1[t] = (s > 0.f) ? s : 0.01f * s;
    }
    __syncthreads();
    if (t < 16) {
        float s = bl2[t];
        for (int k = 0; k < 64; k++) s += Wl2[t * 64 + k] * x1[k];
        x2[t] = (s > 0.f) ? s : 0.01f * s;
    }
    __syncthreads();
    if (t < 16) {
        float s = bl3[t];
        for (int k = 0; k < 16; k++) s += Wl3[t * 16 + k] * x2[k];
        out[t] = fmaxf(s, 0.f);
    }
}

// ---------------- launch ----------------
extern "C" void kernel_launch(void* const* d_in, const int* in_sizes, int n_in,
                              void* d_out, int out_size) {
    const float* x    = (const float*)d_in[0];
    const int*   esrc = (const int*)  d_in[1];
    const int*   edst = (const int*)  d_in[2];
    const float* W1   = (const float*)d_in[3];
    const float* a1   = (const float*)d_in[4];
    const float* W2   = (const float*)d_in[5];
    const float* a2   = (const float*)d_in[6];
    const float* ln_g = (const float*)d_in[7];
    const float* ln_b = (const float*)d_in[8];
    const float* Wl1  = (const float*)d_in[9];
    const float* bl1  = (const float*)d_in[10];
    const float* Wl2  = (const float*)d_in[11];
    const float* bl2  = (const float*)d_in[12];
    const float* Wl3  = (const float*)d_in[13];
    const float* bl3  = (const float*)d_in[14];
    float* out = (float*)d_out;

    // CSR build (re-done every call; deterministic up to fp summation order)
    init_deg_kernel<<<(N_NODES + 255) / 256, 256>>>();
    hist_kernel<<<(N_EDGES + 255) / 256, 256>>>(edst);
    scan_kernel<<<1, 1024>>>();
    fill_kernel<<<(N_EDGES + 255) / 256, 256>>>(esrc, edst);

    dim3 ggrid(NH / BN, (N_NODES + BM - 1) / BM);   // (8, 79)

    // Layer 1
    sgemm_nt<true><<<ggrid, 256>>>(x, W1, N_NODES, NH, N_FEAT);
    scores_kernel<<<(N_NODES * HEADS * 32 + 255) / 256, 256>>>(a1);
    aggregate_kernel<1><<<N_NODES, 256>>>();

    // Layer 2
    sgemm_nt<false><<<ggrid, 256>>>(nullptr, W2, N_NODES, NH, HID);
    scores_kernel<<<(N_NODES * HEADS * 32 + 255) / 256, 256>>>(a2);
    aggregate_kernel<2><<<N_NODES, 256>>>();

    // Pool + head
    pool_stage1<<<128, 128>>>();
    pool_stage2<<<1, 128>>>();
    mlp_kernel<<<1, 128>>>(ln_g, ln_b, Wl1, bl1, Wl2, bl2, Wl3, bl3, out);
}

// round 3
// speedup vs baseline: 1.9383x; 1.9383x over previous
#include <cuda_runtime.h>
#include <cuda_bf16.h>
#include <math.h>
#include <stdint.h>
#include <cstdint>

#define N_NODES 10000
#define N_EDGES 160000
#define N_FEAT  512
#define HEADS   8
#define HID     128
#define NH      (HEADS * HID)   // 1024

// ---------------- scratch (device globals; no allocations allowed) ----------
__device__ float g_h[(size_t)N_NODES * NH];        // projected features [N,H,D]
__device__ float g_emb1[(size_t)N_NODES * HID];
__device__ float g_emb2[(size_t)N_NODES * HID];
__device__ float g_si[N_NODES * HEADS];
__device__ float g_sj[N_NODES * HEADS];
__device__ int   g_deg[N_NODES];
__device__ int   g_off[N_NODES + 1];
__device__ int   g_cur[N_NODES];
__device__ int   g_csr[N_EDGES];
__device__ float g_part[128 * HID];
__device__ float g_gvec[HID];

// ---------------- CSR construction ----------------
__global__ void init_deg_kernel() {
    int i = blockIdx.x * blockDim.x + threadIdx.x;
    if (i < N_NODES) g_deg[i] = 0;
}

__global__ void hist_kernel(const int* __restrict__ dst) {
    int e = blockIdx.x * blockDim.x + threadIdx.x;
    if (e < N_EDGES) atomicAdd(&g_deg[dst[e]], 1);
}

__global__ void scan_kernel() {
    __shared__ int sums[1024];
    int t = threadIdx.x;
    const int CH = (N_NODES + 1023) / 1024;   // 10
    int start = t * CH;
    int s = 0;
    for (int i = 0; i < CH; i++) {
        int idx = start + i;
        if (idx < N_NODES) s += g_deg[idx];
    }
    sums[t] = s;
    __syncthreads();
    for (int st = 1; st < 1024; st <<= 1) {
        int v = (t >= st) ? sums[t - st] : 0;
        __syncthreads();
        sums[t] += v;
        __syncthreads();
    }
    int base = (t == 0) ? 0 : sums[t - 1];
    for (int i = 0; i < CH; i++) {
        int idx = start + i;
        if (idx < N_NODES) {
            g_off[idx] = base;
            g_cur[idx] = base;
            base += g_deg[idx];
        }
    }
    if (t == 1023) g_off[N_NODES] = sums[1023];
}

__global__ void fill_kernel(const int* __restrict__ src, const int* __restrict__ dst) {
    int e = blockIdx.x * blockDim.x + threadIdx.x;
    if (e < N_EDGES) {
        int pos = atomicAdd(&g_cur[dst[e]], 1);
        g_csr[pos] = src[e];
    }
}

// ---------------- TF32 tensor-core GEMM: C[m,n] = sum_k A[m,k]*B[n,k] ------
// C = g_h always. A = arg (layer 1) or g_emb1 (layer 2). M=10000, N=1024,
// K in {512,128}. Block tile 128x128, BK=16, double-buffered cp.async,
// 8 warps (4x2), warp tile 32x64 = 2x8 m16n8k8 fragments.

#define GBM 128
#define GBN 128
#define GBK 16

__device__ __forceinline__ unsigned cvt_tf32(float f) {
    unsigned u;
    asm("cvt.rna.tf32.f32 %0, %1;" : "=r"(u) : "f"(f));
    return u;
}

// swizzled smem offset for a [128][16] float tile (16B-group XOR swizzle)
__device__ __forceinline__ int swoff(int m, int k) {
    return m * GBK + ((((k >> 2) ^ (m >> 1)) & 3) << 2) + (k & 3);
}

__device__ __forceinline__ void mma_tf32(float* c, const unsigned* a, const unsigned* b) {
    asm volatile(
        "mma.sync.aligned.m16n8k8.row.col.f32.tf32.tf32.f32 "
        "{%0,%1,%2,%3}, {%4,%5,%6,%7}, {%8,%9}, {%0,%1,%2,%3};"
        : "+f"(c[0]), "+f"(c[1]), "+f"(c[2]), "+f"(c[3])
        : "r"(a[0]), "r"(a[1]), "r"(a[2]), "r"(a[3]), "r"(b[0]), "r"(b[1]));
}

template<bool A_FROM_ARG>
__global__ __launch_bounds__(256)
void gemm_tf32(const float* __restrict__ Aarg, const float* __restrict__ B,
               int M, int N, int K) {
    const float* A = A_FROM_ARG ? Aarg : g_emb1;
    float* C = g_h;

    __shared__ float As[2][GBM * GBK];
    __shared__ float Bs[2][GBM * GBK];

    int tid = threadIdx.x;
    int lane = tid & 31;
    int wid = tid >> 5;
    int wm = wid & 3;          // 0..3
    int wn = wid >> 2;         // 0..1
    int bm = blockIdx.y * GBM;
    int bn = blockIdx.x * GBN;

    unsigned sA = (unsigned)__cvta_generic_to_shared(&As[0][0]);
    unsigned sB = (unsigned)__cvta_generic_to_shared(&Bs[0][0]);

    float acc[2][8][4];
    #pragma unroll
    for (int mi = 0; mi < 2; mi++)
        #pragma unroll
        for (int ni = 0; ni < 8; ni++)
            #pragma unroll
            for (int r = 0; r < 4; r++) acc[mi][ni][r] = 0.f;

    const int nch = K / GBK;

    auto load_tile = [&](int c, int s) {
        #pragma unroll
        for (int i = 0; i < 2; i++) {
            int id  = tid + i * 256;     // 0..511
            int row = id >> 2;           // 0..127
            int g   = id & 3;
            int soff = (s * (GBM * GBK) + row * GBK + (((g ^ (row >> 1)) & 3) << 2)) << 2;
            // A (may be out of range in M)
            {
                int gm = bm + row;
                const float* src = A + (size_t)(gm < M ? gm : (M - 1)) * K + c * GBK + g * 4;
                int sz = (gm < M) ? 16 : 0;
                asm volatile("cp.async.cg.shared.global [%0], [%1], 16, %2;\n"
                             :: "r"(sA + soff), "l"(src), "r"(sz));
            }
            // B (always in range: N multiple of 128)
            {
                const float* src = B + (size_t)(bn + row) * K + c * GBK + g * 4;
                asm volatile("cp.async.cg.shared.global [%0], [%1], 16;\n"
                             :: "r"(sB + soff), "l"(src));
            }
        }
    };

    load_tile(0, 0);
    asm volatile("cp.async.commit_group;\n");

    for (int c = 0; c < nch; c++) {
        int buf = c & 1;
        if (c + 1 < nch) {
            load_tile(c + 1, buf ^ 1);
            asm volatile("cp.async.commit_group;\n");
            asm volatile("cp.async.wait_group 1;\n");
        } else {
            asm volatile("cp.async.wait_group 0;\n");
        }
        __syncthreads();

        #pragma unroll
        for (int ks = 0; ks < GBK / 8; ks++) {
            int kk = ks * 8 + (lane & 3);
            unsigned af[2][4];
            #pragma unroll
            for (int mi = 0; mi < 2; mi++) {
                int m0 = wm * 32 + mi * 16 + (lane >> 2);
                int m1 = m0 + 8;
                af[mi][0] = cvt_tf32(As[buf][swoff(m0, kk)]);
                af[mi][1] = cvt_tf32(As[buf][swoff(m1, kk)]);
                af[mi][2] = cvt_tf32(As[buf][swoff(m0, kk + 4)]);
                af[mi][3] = cvt_tf32(As[buf][swoff(m1, kk + 4)]);
            }
            unsigned bf[8][2];
            #pragma unroll
            for (int ni = 0; ni < 8; ni++) {
                int n0 = wn * 64 + ni * 8 + (lane >> 2);
                bf[ni][0] = cvt_tf32(Bs[buf][swoff(n0, kk)]);
                bf[ni][1] = cvt_tf32(Bs[buf][swoff(n0, kk + 4)]);
            }
            #pragma unroll
            for (int mi = 0; mi < 2; mi++)
                #pragma unroll
                for (int ni = 0; ni < 8; ni++)
                    mma_tf32(acc[mi][ni], af[mi], bf[ni]);
        }
        __syncthreads();
    }

    // epilogue
    #pragma unroll
    for (int mi = 0; mi < 2; mi++) {
        int m0 = bm + wm * 32 + mi * 16 + (lane >> 2);
        int m1 = m0 + 8;
        #pragma unroll
        for (int ni = 0; ni < 8; ni++) {
            int nc = bn + wn * 64 + ni * 8 + (lane & 3) * 2;
            if (m0 < M) {
                float2 v = make_float2(acc[mi][ni][0], acc[mi][ni][1]);
                *reinterpret_cast<float2*>(&C[(size_t)m0 * N + nc]) = v;
            }
            if (m1 < M) {
                float2 v = make_float2(acc[mi][ni][2], acc[mi][ni][3]);
                *reinterpret_cast<float2*>(&C[(size_t)m1 * N + nc]) = v;
            }
        }
    }
}

// ---------------- attention scores: s_i / s_j per (node, head) -------------
__global__ void scores_kernel(const float* __restrict__ a) {
    int gw = (blockIdx.x * blockDim.x + threadIdx.x) >> 5;
    int lane = threadIdx.x & 31;
    if (gw >= N_NODES * HEADS) return;
    int n = gw / HEADS, hd = gw % HEADS;
    const float* hp = g_h + ((size_t)n * HEADS + hd) * HID;
    const float* ap = a + hd * 2 * HID;
    float s1 = 0.f, s2 = 0.f;
    #pragma unroll
    for (int j = 0; j < HID / 32; j++) {
        int d = lane + 32 * j;
        float v = hp[d];
        s1 += v * ap[d];
        s2 += v * ap[HID + d];
    }
    #pragma unroll
    for (int o = 16; o; o >>= 1) {
        s1 += __shfl_down_sync(0xffffffffu, s1, o);
        s2 += __shfl_down_sync(0xffffffffu, s2, o);
    }
    if (lane == 0) { g_si[gw] = s1; g_sj[gw] = s2; }
}

// ---------------- aggregation: segment softmax + weighted gather -----------
template<int OUT>
__global__ __launch_bounds__(256)
void aggregate_kernel() {
    int n = blockIdx.x;
    int w = threadIdx.x >> 5;
    int lane = threadIdx.x & 31;
    __shared__ float part[HEADS][HID];

    int off = g_off[n], end = g_off[n + 1];
    float si_v = g_si[n * HEADS + w];
    float4 acc = make_float4(0.f, 0.f, 0.f, 0.f);
    float m_run = -INFINITY, d_run = 0.f;

    for (int base = off; base < end; base += 32) {
        int e = base + lane;
        int src = 0;
        float ev = -INFINITY;
        if (e < end) {
            src = g_csr[e];
            float x = si_v + g_sj[src * HEADS + w];
            ev = (x > 0.f) ? x : 0.01f * x;
        }
        float cm = ev;
        #pragma unroll
        for (int o = 16; o; o >>= 1) cm = fmaxf(cm, __shfl_xor_sync(0xffffffffu, cm, o));
        float new_m = fmaxf(m_run, cm);
        float p = (e < end) ? __expf(ev - new_m) : 0.f;
        float ps = p;
        #pragma unroll
        for (int o = 16; o; o >>= 1) ps += __shfl_xor_sync(0xffffffffu, ps, o);
        float scale = (m_run == -INFINITY) ? 0.f : __expf(m_run - new_m);
        d_run = d_run * scale + ps;
        acc.x *= scale; acc.y *= scale; acc.z *= scale; acc.w *= scale;
        m_run = new_m;

        int cnt = min(32, end - base);
        for (int j = 0; j < cnt; j++) {
            float pj = __shfl_sync(0xffffffffu, p, j);
            int sidx = __shfl_sync(0xffffffffu, src, j);
            const float4 v = *reinterpret_cast<const float4*>(
                &g_h[((size_t)sidx * HEADS + w) * HID + lane * 4]);
            acc.x += pj * v.x; acc.y += pj * v.y;
            acc.z += pj * v.z; acc.w += pj * v.w;
        }
    }
    if (d_run > 0.f) {
        float inv = 1.f / d_run;
        acc.x *= inv; acc.y *= inv; acc.z *= inv; acc.w *= inv;
    }
    part[w][lane * 4 + 0] = acc.x;
    part[w][lane * 4 + 1] = acc.y;
    part[w][lane * 4 + 2] = acc.z;
    part[w][lane * 4 + 3] = acc.w;
    __syncthreads();

    if (threadIdx.x < HID) {
        int d = threadIdx.x;
        float s = 0.f;
        #pragma unroll
        for (int hh = 0; hh < HEADS; hh++) s += part[hh][d];
        s *= (1.f / HEADS);
        float o = (s > 0.f) ? s : (__expf(s) - 1.f);   // ELU
        float* emb = (OUT == 1) ? g_emb1 : g_emb2;
        emb[(size_t)n * HID + d] = o;
    }
}

// ---------------- graph mean pooling ----------------
__global__ void pool_stage1() {
    const int RP = (N_NODES + 127) / 128;   // 79
    int b = blockIdx.x, d = threadIdx.x;
    int r0 = b * RP;
    int r1 = min(r0 + RP, N_NODES);
    float s = 0.f;
    for (int r = r0; r < r1; r++) s += g_emb2[(size_t)r * HID + d];
    g_part[b * HID + d] = s;
}

__global__ void pool_stage2() {
    int d = threadIdx.x;
    float s = 0.f;
    for (int b = 0; b < 128; b++) s += g_part[b * HID + d];
    g_gvec[d] = s * (1.f / N_NODES);
}

// ---------------- MLP head ----------------
__global__ void mlp_kernel(const float* __restrict__ ln_g, const float* __restrict__ ln_b,
                           const float* __restrict__ Wl1, const float* __restrict__ bl1,
                           const float* __restrict__ Wl2, const float* __restrict__ bl2,
                           const float* __restrict__ Wl3, const float* __restrict__ bl3,
                           float* __restrict__ out) {
    __shared__ float gn[HID];
    __shared__ float x1[64];
    __shared__ float x2[16];
    __shared__ float red[128];
    int t = threadIdx.x;  // 128 threads
    float gv = g_gvec[t];

    red[t] = gv;
    __syncthreads();
    for (int st = 64; st; st >>= 1) {
        if (t < st) red[t] += red[t + st];
        __syncthreads();
    }
    float mu = red[0] * (1.f / HID);
    __syncthreads();

    float dv = gv - mu;
    red[t] = dv * dv;
    __syncthreads();
    for (int st = 64; st; st >>= 1) {
        if (t < st) red[t] += red[t + st];
        __syncthreads();
    }
    float var = red[0] * (1.f / HID);
    gn[t] = dv * rsqrtf(var + 1e-5f) * ln_g[t] + ln_b[t];
    __syncthreads();

    if (t < 64) {
        float s = bl1[t];
        for (int k = 0; k < HID; k++) s += Wl1[t * HID + k] * gn[k];
        x1[t] = (s > 0.f) ? s : 0.01f * s;
    }
    __syncthreads();
    if (t < 16) {
        float s = bl2[t];
        for (int k = 0; k < 64; k++) s += Wl2[t * 64 + k] * x1[k];
        x2[t] = (s > 0.f) ? s : 0.01f * s;
    }
    __syncthreads();
    if (t < 16) {
        float s = bl3[t];
        for (int k = 0; k < 16; k++) s += Wl3[t * 16 + k] * x2[k];
        out[t] = fmaxf(s, 0.f);
    }
}

// ---------------- launch ----------------
extern "C" void kernel_launch(void* const* d_in, const int* in_sizes, int n_in,
                              void* d_out, int out_size) {
    const float* x    = (const float*)d_in[0];
    const int*   esrc = (const int*)  d_in[1];
    const int*   edst = (const int*)  d_in[2];
    const float* W1   = (const float*)d_in[3];
    const float* a1   = (const float*)d_in[4];
    const float* W2   = (const float*)d_in[5];
    const float* a2   = (const float*)d_in[6];
    const float* ln_g = (const float*)d_in[7];
    const float* ln_b = (const float*)d_in[8];
    const float* Wl1  = (const float*)d_in[9];
    const float* bl1  = (const float*)d_in[10];
    const float* Wl2  = (const float*)d_in[11];
    const float* bl2  = (const float*)d_in[12];
    const float* Wl3  = (const float*)d_in[13];
    const float* bl3  = (const float*)d_in[14];
    float* out = (float*)d_out;

    // CSR build
    init_deg_kernel<<<(N_NODES + 255) / 256, 256>>>();
    hist_kernel<<<(N_EDGES + 255) / 256, 256>>>(edst);
    scan_kernel<<<1, 1024>>>();
    fill_kernel<<<(N_EDGES + 255) / 256, 256>>>(esrc, edst);

    dim3 ggrid(NH / GBN, (N_NODES + GBM - 1) / GBM);   // (8, 79)

    // Layer 1
    gemm_tf32<true><<<ggrid, 256>>>(x, W1, N_NODES, NH, N_FEAT);
    scores_kernel<<<(N_NODES * HEADS * 32 + 255) / 256, 256>>>(a1);
    aggregate_kernel<1><<<N_NODES, 256>>>();

    // Layer 2
    gemm_tf32<false><<<ggrid, 256>>>(nullptr, W2, N_NODES, NH, HID);
    scores_kernel<<<(N_NODES * HEADS * 32 + 255) / 256, 256>>>(a2);
    aggregate_kernel<2><<<N_NODES, 256>>>();

    // Pool + head
    pool_stage1<<<128, 128>>>();
    pool_stage2<<<1, 128>>>();
    mlp_kernel<<<1, 128>>>(ln_g, ln_b, Wl1, bl1, Wl2, bl2, Wl3, bl3, out);
}